// round 3
// baseline (speedup 1.0000x reference)
#include <cuda_runtime.h>

#define B_  4
#define T_  2048
#define D_  1024
#define H_  16
#define HD_ 64
#define M_  (B_*T_)

// Scratch (allocation-free): Q/K/V in [B,H,T,Hd] layout, attention output in [B,T,D].
__device__ float g_q[(size_t)B_*H_*T_*HD_];
__device__ float g_k[(size_t)B_*H_*T_*HD_];
__device__ float g_v[(size_t)B_*H_*T_*HD_];
__device__ float g_att[(size_t)M_*D_];

// ---------------------------------------------------------------------------
// Kernel 1: QKV GEMM.  C[8192,3072] = X[8192,1024] @ W[1024,3072] + b,
// scattered into g_q/g_k/g_v in [B,H,T,Hd] layout. Each 64-wide column tile
// maps to exactly one (three, head), so the scatter is trivial.
// ---------------------------------------------------------------------------
__global__ __launch_bounds__(256) void qkv_gemm_kernel(
    const float* __restrict__ X, const float* __restrict__ W,
    const float* __restrict__ bias)
{
    __shared__ float Xs[16][65];   // transposed [k][m], padded
    __shared__ float Ws[16][64];   // [k][n]
    const int tid = threadIdx.x;
    const int tx = tid & 15, ty = tid >> 4;
    const int n0 = blockIdx.x << 6;
    const int m0 = blockIdx.y << 6;
    const int lxr = tid >> 2,  lxc = (tid & 3)  << 2;
    const int lwr = tid >> 4,  lwc = (tid & 15) << 2;

    float acc[4][4] = {};
    for (int k0 = 0; k0 < D_; k0 += 16) {
        float4 xv = *(const float4*)(X + (size_t)(m0 + lxr) * D_ + k0 + lxc);
        Xs[lxc + 0][lxr] = xv.x;
        Xs[lxc + 1][lxr] = xv.y;
        Xs[lxc + 2][lxr] = xv.z;
        Xs[lxc + 3][lxr] = xv.w;
        *(float4*)&Ws[lwr][lwc] =
            *(const float4*)(W + (size_t)(k0 + lwr) * (3 * D_) + n0 + lwc);
        __syncthreads();
#pragma unroll
        for (int k = 0; k < 16; k++) {
            float a0 = Xs[k][ty*4+0], a1 = Xs[k][ty*4+1];
            float a2 = Xs[k][ty*4+2], a3 = Xs[k][ty*4+3];
            float4 b4 = *(float4*)&Ws[k][tx*4];
            acc[0][0] += a0*b4.x; acc[0][1] += a0*b4.y; acc[0][2] += a0*b4.z; acc[0][3] += a0*b4.w;
            acc[1][0] += a1*b4.x; acc[1][1] += a1*b4.y; acc[1][2] += a1*b4.z; acc[1][3] += a1*b4.w;
            acc[2][0] += a2*b4.x; acc[2][1] += a2*b4.y; acc[2][2] += a2*b4.z; acc[2][3] += a2*b4.w;
            acc[3][0] += a3*b4.x; acc[3][1] += a3*b4.y; acc[3][2] += a3*b4.z; acc[3][3] += a3*b4.w;
        }
        __syncthreads();
    }

    // Epilogue: this n-tile is exactly one (three, head) pair.
    const int three = n0 >> 10;            // 0:q 1:k 2:v
    const int h     = (n0 & 1023) >> 6;
    float* dst = (three == 0) ? g_q : ((three == 1) ? g_k : g_v);
    const float* brow = bias + n0 + (tx << 2);
    float bb0 = brow[0], bb1 = brow[1], bb2 = brow[2], bb3 = brow[3];
#pragma unroll
    for (int i = 0; i < 4; i++) {
        int m = m0 + ty*4 + i;
        int b = m >> 11;                   // /T_
        int t = m & 2047;
        float4 o;
        o.x = acc[i][0] + bb0;
        o.y = acc[i][1] + bb1;
        o.z = acc[i][2] + bb2;
        o.w = acc[i][3] + bb3;
        *(float4*)(dst + ((size_t)(b*H_ + h)*T_ + t) * HD_ + (tx << 2)) = o;
    }
}

// ---------------------------------------------------------------------------
// Kernel 2: flash attention (online softmax), fp32.
// grid = (T/64, B*H). Block = 256 threads, 4x4 micro-tile over a 64x64 S tile.
// Causal: only key tiles kt <= qt are processed.
// ---------------------------------------------------------------------------
__global__ __launch_bounds__(256) void attn_kernel()
{
    extern __shared__ float sm[];
    float (*Qs)[65] = (float(*)[65])(sm);
    float (*Ks)[65] = (float(*)[65])(sm + 64*65);
    float (*Vs)[65] = (float(*)[65])(sm + 2*64*65);
    float (*Ps)[65] = (float(*)[65])(sm + 3*64*65);

    const int tid = threadIdx.x;
    const int tx = tid & 15, ty = tid >> 4;
    const int qt = blockIdx.x;
    const int bh = blockIdx.y;
    const int m0 = qt << 6;
    const float scale = 0.125f;            // 1/sqrt(64)

    const float* Qg = g_q + (size_t)bh * T_ * HD_;
    const float* Kg = g_k + (size_t)bh * T_ * HD_;
    const float* Vg = g_v + (size_t)bh * T_ * HD_;

    // Load Q tile once (coalesced float4, scalar smem stores).
#pragma unroll
    for (int l = 0; l < 4; l++) {
        int v = tid + (l << 8);
        int r = v >> 4, c = (v & 15) << 2;
        float4 q4 = *(const float4*)(Qg + (size_t)(m0 + r) * HD_ + c);
        Qs[r][c+0] = q4.x; Qs[r][c+1] = q4.y; Qs[r][c+2] = q4.z; Qs[r][c+3] = q4.w;
    }

    float m_i[4], l_i[4], o[4][4];
#pragma unroll
    for (int i = 0; i < 4; i++) {
        m_i[i] = -1e30f; l_i[i] = 0.0f;
#pragma unroll
        for (int j = 0; j < 4; j++) o[i][j] = 0.0f;
    }

    for (int kt = 0; kt <= qt; kt++) {
        __syncthreads();   // protect Ks/Vs/Ps from previous iteration readers
#pragma unroll
        for (int l = 0; l < 4; l++) {
            int v = tid + (l << 8);
            int r = v >> 4, c = (v & 15) << 2;
            const size_t gofs = (size_t)((kt << 6) + r) * HD_ + c;
            float4 k4 = *(const float4*)(Kg + gofs);
            Ks[r][c+0] = k4.x; Ks[r][c+1] = k4.y; Ks[r][c+2] = k4.z; Ks[r][c+3] = k4.w;
            float4 v4 = *(const float4*)(Vg + gofs);
            Vs[r][c+0] = v4.x; Vs[r][c+1] = v4.y; Vs[r][c+2] = v4.z; Vs[r][c+3] = v4.w;
        }
        __syncthreads();

        // S = Q K^T (4x4 per thread)
        float s[4][4] = {};
#pragma unroll 8
        for (int d = 0; d < 64; d++) {
            float a0 = Qs[ty*4+0][d], a1 = Qs[ty*4+1][d];
            float a2 = Qs[ty*4+2][d], a3 = Qs[ty*4+3][d];
            float b0 = Ks[tx*4+0][d], b1 = Ks[tx*4+1][d];
            float b2 = Ks[tx*4+2][d], b3 = Ks[tx*4+3][d];
            s[0][0] += a0*b0; s[0][1] += a0*b1; s[0][2] += a0*b2; s[0][3] += a0*b3;
            s[1][0] += a1*b0; s[1][1] += a1*b1; s[1][2] += a1*b2; s[1][3] += a1*b3;
            s[2][0] += a2*b0; s[2][1] += a2*b1; s[2][2] += a2*b2; s[2][3] += a2*b3;
            s[3][0] += a3*b0; s[3][1] += a3*b1; s[3][2] += a3*b2; s[3][3] += a3*b3;
        }
#pragma unroll
        for (int i = 0; i < 4; i++)
#pragma unroll
            for (int j = 0; j < 4; j++) s[i][j] *= scale;

        if (kt == qt) {   // diagonal tile: causal mask within tile
#pragma unroll
            for (int i = 0; i < 4; i++)
#pragma unroll
                for (int j = 0; j < 4; j++)
                    if ((tx<<2) + j > (ty<<2) + i) s[i][j] = -1e30f;
        }

        // Row max over 16 lanes sharing ty (lanes stay in their 16-half of the warp).
        float alpha[4];
#pragma unroll
        for (int i = 0; i < 4; i++) {
            float v = fmaxf(fmaxf(s[i][0], s[i][1]), fmaxf(s[i][2], s[i][3]));
#pragma unroll
            for (int off = 1; off < 16; off <<= 1)
                v = fmaxf(v, __shfl_xor_sync(0xffffffffu, v, off));
            float mn = fmaxf(m_i[i], v);
            alpha[i] = __expf(m_i[i] - mn);
            m_i[i] = mn;
        }

        // p = exp(s - m), row sum
        float rs[4];
#pragma unroll
        for (int i = 0; i < 4; i++) {
            rs[i] = 0.0f;
#pragma unroll
            for (int j = 0; j < 4; j++) {
                s[i][j] = __expf(s[i][j] - m_i[i]);
                rs[i] += s[i][j];
            }
#pragma unroll
            for (int off = 1; off < 16; off <<= 1)
                rs[i] += __shfl_xor_sync(0xffffffffu, rs[i], off);
            l_i[i] = l_i[i] * alpha[i] + rs[i];
        }

        // Publish P, then O += P @ V
#pragma unroll
        for (int i = 0; i < 4; i++)
#pragma unroll
            for (int j = 0; j < 4; j++)
                Ps[ty*4+i][tx*4+j] = s[i][j];
        __syncthreads();

#pragma unroll
        for (int i = 0; i < 4; i++)
#pragma unroll
            for (int j = 0; j < 4; j++) o[i][j] *= alpha[i];

#pragma unroll 8
        for (int c = 0; c < 64; c++) {
            float p0 = Ps[ty*4+0][c], p1 = Ps[ty*4+1][c];
            float p2 = Ps[ty*4+2][c], p3 = Ps[ty*4+3][c];
            float v0 = Vs[c][tx*4+0], v1 = Vs[c][tx*4+1];
            float v2 = Vs[c][tx*4+2], v3 = Vs[c][tx*4+3];
            o[0][0] += p0*v0; o[0][1] += p0*v1; o[0][2] += p0*v2; o[0][3] += p0*v3;
            o[1][0] += p1*v0; o[1][1] += p1*v1; o[1][2] += p1*v2; o[1][3] += p1*v3;
            o[2][0] += p2*v0; o[2][1] += p2*v1; o[2][2] += p2*v2; o[2][3] += p2*v3;
            o[3][0] += p3*v0; o[3][1] += p3*v1; o[3][2] += p3*v2; o[3][3] += p3*v3;
        }
    }

    // Write normalized output to g_att [B,T,D]
    const int b = bh / H_;
    const int h = bh % H_;
#pragma unroll
    for (int i = 0; i < 4; i++) {
        int t = m0 + ty*4 + i;
        float inv = 1.0f / l_i[i];
        float4 r;
        r.x = o[i][0] * inv; r.y = o[i][1] * inv;
        r.z = o[i][2] * inv; r.w = o[i][3] * inv;
        *(float4*)(g_att + (size_t)(b*T_ + t) * D_ + h*HD_ + (tx << 2)) = r;
    }
}

// ---------------------------------------------------------------------------
// Kernel 3: output projection.  out[8192,1024] = g_att @ Wp[1024,1024] + bp
// ---------------------------------------------------------------------------
__global__ __launch_bounds__(256) void proj_gemm_kernel(
    const float* __restrict__ W, const float* __restrict__ bias,
    float* __restrict__ C)
{
    __shared__ float Xs[16][65];
    __shared__ float Ws[16][64];
    const int tid = threadIdx.x;
    const int tx = tid & 15, ty = tid >> 4;
    const int n0 = blockIdx.x << 6;
    const int m0 = blockIdx.y << 6;
    const int lxr = tid >> 2,  lxc = (tid & 3)  << 2;
    const int lwr = tid >> 4,  lwc = (tid & 15) << 2;

    float acc[4][4] = {};
    for (int k0 = 0; k0 < D_; k0 += 16) {
        float4 xv = *(const float4*)(g_att + (size_t)(m0 + lxr) * D_ + k0 + lxc);
        Xs[lxc + 0][lxr] = xv.x;
        Xs[lxc + 1][lxr] = xv.y;
        Xs[lxc + 2][lxr] = xv.z;
        Xs[lxc + 3][lxr] = xv.w;
        *(float4*)&Ws[lwr][lwc] =
            *(const float4*)(W + (size_t)(k0 + lwr) * D_ + n0 + lwc);
        __syncthreads();
#pragma unroll
        for (int k = 0; k < 16; k++) {
            float a0 = Xs[k][ty*4+0], a1 = Xs[k][ty*4+1];
            float a2 = Xs[k][ty*4+2], a3 = Xs[k][ty*4+3];
            float4 b4 = *(float4*)&Ws[k][tx*4];
            acc[0][0] += a0*b4.x; acc[0][1] += a0*b4.y; acc[0][2] += a0*b4.z; acc[0][3] += a0*b4.w;
            acc[1][0] += a1*b4.x; acc[1][1] += a1*b4.y; acc[1][2] += a1*b4.z; acc[1][3] += a1*b4.w;
            acc[2][0] += a2*b4.x; acc[2][1] += a2*b4.y; acc[2][2] += a2*b4.z; acc[2][3] += a2*b4.w;
            acc[3][0] += a3*b4.x; acc[3][1] += a3*b4.y; acc[3][2] += a3*b4.z; acc[3][3] += a3*b4.w;
        }
        __syncthreads();
    }

    const float* brow = bias + n0 + (tx << 2);
    float bb0 = brow[0], bb1 = brow[1], bb2 = brow[2], bb3 = brow[3];
#pragma unroll
    for (int i = 0; i < 4; i++) {
        int m = m0 + ty*4 + i;
        float4 o;
        o.x = acc[i][0] + bb0;
        o.y = acc[i][1] + bb1;
        o.z = acc[i][2] + bb2;
        o.w = acc[i][3] + bb3;
        *(float4*)(C + (size_t)m * D_ + n0 + (tx << 2)) = o;
    }
}

// ---------------------------------------------------------------------------
extern "C" void kernel_launch(void* const* d_in, const int* in_sizes, int n_in,
                              void* d_out, int out_size)
{
    const float* x      = (const float*)d_in[0];
    const float* w_qkv  = (const float*)d_in[1];
    const float* b_qkv  = (const float*)d_in[2];
    const float* w_proj = (const float*)d_in[3];
    const float* b_proj = (const float*)d_in[4];
    float* out = (float*)d_out;

    // 1) QKV projection + scatter to [B,H,T,Hd]
    qkv_gemm_kernel<<<dim3(3*D_/64, M_/64), 256>>>(x, w_qkv, b_qkv);

    // 2) causal flash attention
    const int attn_smem = 4 * 64 * 65 * (int)sizeof(float);   // 66,560 B
    cudaFuncSetAttribute(attn_kernel,
                         cudaFuncAttributeMaxDynamicSharedMemorySize, attn_smem);
    attn_kernel<<<dim3(T_/64, B_*H_), 256, attn_smem>>>();

    // 3) output projection
    proj_gemm_kernel<<<dim3(D_/64, M_/64), 256>>>(w_proj, b_proj, out);
}

// round 6
// speedup vs baseline: 1.7015x; 1.7015x over previous
#include <cuda_runtime.h>
#include <cuda_bf16.h>
#include <cstdint>

#define B_  4
#define T_  2048
#define D_  1024
#define H_  16
#define HD_ 64
#define M_  (B_*T_)
#define NQKV (3*D_)
#define GK   1024

// ---------------------------------------------------------------------------
// Scratch (allocation-free __device__ globals)
// ---------------------------------------------------------------------------
__device__ float g_q[(size_t)B_*H_*T_*HD_];
__device__ float g_k[(size_t)B_*H_*T_*HD_];
__device__ float g_v[(size_t)B_*H_*T_*HD_];
__device__ float g_att[(size_t)M_*D_];

// split-bf16 operands
__device__ __nv_bfloat16 g_xhi[(size_t)M_*D_];
__device__ __nv_bfloat16 g_xlo[(size_t)M_*D_];
__device__ __nv_bfloat16 g_wqkv_hi[(size_t)NQKV*D_];   // transposed [N,K]
__device__ __nv_bfloat16 g_wqkv_lo[(size_t)NQKV*D_];
__device__ __nv_bfloat16 g_wp_hi[(size_t)D_*D_];       // transposed [N,K]
__device__ __nv_bfloat16 g_wp_lo[(size_t)D_*D_];
__device__ __nv_bfloat16 g_atthi[(size_t)M_*D_];
__device__ __nv_bfloat16 g_attlo[(size_t)M_*D_];

// ---------------------------------------------------------------------------
// Helpers (all plain sm_80+ PTX; nothing arch-'a'-gated)
// ---------------------------------------------------------------------------
__device__ __forceinline__ uint32_t smem_u32_of(const void* p) {
    uint32_t a;
    asm("{ .reg .u64 t; cvta.to.shared.u64 t, %1; cvt.u32.u64 %0, t; }" : "=r"(a) : "l"(p));
    return a;
}

__device__ __forceinline__ void cp_async16(uint32_t saddr, const void* gptr) {
    asm volatile("cp.async.cg.shared.global [%0], [%1], 16;"
                 :: "r"(saddr), "l"(gptr) : "memory");
}

__device__ __forceinline__ void mma_bf16(float* c, const uint32_t* a, const uint32_t* b) {
    asm volatile(
        "mma.sync.aligned.m16n8k16.row.col.f32.bf16.bf16.f32 "
        "{%0,%1,%2,%3}, {%4,%5,%6,%7}, {%8,%9}, {%0,%1,%2,%3};"
        : "+f"(c[0]), "+f"(c[1]), "+f"(c[2]), "+f"(c[3])
        : "r"(a[0]), "r"(a[1]), "r"(a[2]), "r"(a[3]), "r"(b[0]), "r"(b[1]));
}

// ---------------------------------------------------------------------------
// Split fp32 -> (hi, lo) bf16, elementwise (layout preserved)
// ---------------------------------------------------------------------------
__global__ __launch_bounds__(256) void split_kernel(
    const float* __restrict__ in, __nv_bfloat16* __restrict__ hi,
    __nv_bfloat16* __restrict__ lo, int n4)
{
    int i = blockIdx.x * blockDim.x + threadIdx.x;
    if (i >= n4) return;
    float4 v = ((const float4*)in)[i];
    __nv_bfloat16 h0 = __float2bfloat16(v.x), h1 = __float2bfloat16(v.y);
    __nv_bfloat16 h2 = __float2bfloat16(v.z), h3 = __float2bfloat16(v.w);
    __nv_bfloat16 l0 = __float2bfloat16(v.x - __bfloat162float(h0));
    __nv_bfloat16 l1 = __float2bfloat16(v.y - __bfloat162float(h1));
    __nv_bfloat16 l2 = __float2bfloat16(v.z - __bfloat162float(h2));
    __nv_bfloat16 l3 = __float2bfloat16(v.w - __bfloat162float(h3));
    ((__nv_bfloat162*)hi)[i*2+0] = __nv_bfloat162(h0, h1);
    ((__nv_bfloat162*)hi)[i*2+1] = __nv_bfloat162(h2, h3);
    ((__nv_bfloat162*)lo)[i*2+0] = __nv_bfloat162(l0, l1);
    ((__nv_bfloat162*)lo)[i*2+1] = __nv_bfloat162(l2, l3);
}

// ---------------------------------------------------------------------------
// Transpose + split: W[K,N] fp32 -> Wt_hi/lo[N,K] bf16
// ---------------------------------------------------------------------------
__global__ __launch_bounds__(256) void transpose_split_kernel(
    const float* __restrict__ W, __nv_bfloat16* __restrict__ hi,
    __nv_bfloat16* __restrict__ lo, int K, int N)
{
    __shared__ float tile[32][33];
    const int tx = threadIdx.x, ty = threadIdx.y;
    const int n0 = blockIdx.x * 32, k0 = blockIdx.y * 32;
#pragma unroll
    for (int i = 0; i < 32; i += 8)
        tile[ty + i][tx] = W[(size_t)(k0 + ty + i) * N + n0 + tx];
    __syncthreads();
#pragma unroll
    for (int i = 0; i < 32; i += 8) {
        float v = tile[tx][ty + i];
        __nv_bfloat16 h = __float2bfloat16(v);
        __nv_bfloat16 l = __float2bfloat16(v - __bfloat162float(h));
        size_t o = (size_t)(n0 + ty + i) * K + (k0 + tx);
        hi[o] = h; lo[o] = l;
    }
}

// ---------------------------------------------------------------------------
// HMMA split-bf16 GEMM: C[M,N] = A[M,K] @ Bt[N,K]^T + bias  (3-term split)
// Block 128x128, 8 warps (2m x 4n), warp tile 64x32, K-chunk 32,
// double-buffered cp.async pipeline.
// Smem row padding: 32 bf16 data + 8 pad = 40 bf16 = 80 B = 20 words.
// ---------------------------------------------------------------------------
#define BKC      32
#define NCHUNK   (GK/BKC)            // 32
#define ROW_W    20                  // words per padded smem row
#define OPB      10240               // bytes per operand buffer (128*80)
#define STAGE_B  (4*OPB)             // 40960
#define GEMM_SMEM (2*STAGE_B)        // 81920

__global__ __launch_bounds__(256) void hmma_gemm_kernel(
    const __nv_bfloat16* __restrict__ Ahi, const __nv_bfloat16* __restrict__ Alo,
    const __nv_bfloat16* __restrict__ Bhi, const __nv_bfloat16* __restrict__ Blo,
    const float* __restrict__ bias, float* __restrict__ outp, int qkv_mode)
{
    extern __shared__ char smem[];
    const int tid  = threadIdx.x;
    const int lane = tid & 31;
    const int wid  = tid >> 5;
    const int warp_m = wid & 1;      // 0..1 -> 64 rows each
    const int warp_n = wid >> 1;     // 0..3 -> 32 cols each
    const int n0 = blockIdx.x << 7;
    const int m0 = blockIdx.y << 7;

    const __nv_bfloat16* gops[4] = {
        Ahi + (size_t)m0 * GK, Alo + (size_t)m0 * GK,
        Bhi + (size_t)n0 * GK, Blo + (size_t)n0 * GK };

    // ---- cp.async stage loader: chunk c -> stage s ----
    auto stage_load = [&](int c, int s) {
#pragma unroll
        for (int op = 0; op < 4; op++) {
            char* sd = smem + s * STAGE_B + op * OPB;
            const __nv_bfloat16* g = gops[op];
#pragma unroll
            for (int rep = 0; rep < 2; rep++) {
                int idx = tid + (rep << 8);
                int row = idx >> 2, q = idx & 3;
                uint32_t da = smem_u32_of(sd + row * 80 + q * 16);
                cp_async16(da, (const char*)(g + (size_t)row * GK + c * BKC) + q * 16);
            }
        }
    };

    float acc[4][4][4];
#pragma unroll
    for (int i = 0; i < 4; i++)
#pragma unroll
        for (int j = 0; j < 4; j++)
#pragma unroll
            for (int r = 0; r < 4; r++) acc[i][j][r] = 0.0f;

    stage_load(0, 0);
    asm volatile("cp.async.commit_group;" ::: "memory");

    for (int c = 0; c < NCHUNK; c++) {
        if (c + 1 < NCHUNK) {
            stage_load(c + 1, (c + 1) & 1);
            asm volatile("cp.async.commit_group;" ::: "memory");
            asm volatile("cp.async.wait_group 1;" ::: "memory");
        } else {
            asm volatile("cp.async.wait_group 0;" ::: "memory");
        }
        __syncthreads();

        const uint32_t* sAh = (const uint32_t*)(smem + (c & 1) * STAGE_B);
        const uint32_t* sAl = sAh + OPB / 4;
        const uint32_t* sBh = sAl + OPB / 4;
        const uint32_t* sBl = sBh + OPB / 4;

#pragma unroll
        for (int ks = 0; ks < 2; ks++) {
            const int aw = ks * 8 + (lane & 3);
            const int ar = warp_m * 64 + (lane >> 2);
            uint32_t ah[4][4], al[4][4], bh[4][2], bl[4][2];
#pragma unroll
            for (int wm = 0; wm < 4; wm++) {
                int r0 = (ar + wm * 16) * ROW_W;
                int r8 = (ar + wm * 16 + 8) * ROW_W;
                ah[wm][0] = sAh[r0 + aw];   ah[wm][1] = sAh[r8 + aw];
                ah[wm][2] = sAh[r0 + aw+4]; ah[wm][3] = sAh[r8 + aw+4];
                al[wm][0] = sAl[r0 + aw];   al[wm][1] = sAl[r8 + aw];
                al[wm][2] = sAl[r0 + aw+4]; al[wm][3] = sAl[r8 + aw+4];
            }
#pragma unroll
            for (int wn = 0; wn < 4; wn++) {
                int br = (warp_n * 32 + wn * 8 + (lane >> 2)) * ROW_W;
                bh[wn][0] = sBh[br + aw]; bh[wn][1] = sBh[br + aw + 4];
                bl[wn][0] = sBl[br + aw]; bl[wn][1] = sBl[br + aw + 4];
            }
#pragma unroll
            for (int wm = 0; wm < 4; wm++)
#pragma unroll
                for (int wn = 0; wn < 4; wn++) {
                    mma_bf16(acc[wm][wn], ah[wm], bh[wn]);
                    mma_bf16(acc[wm][wn], ah[wm], bl[wn]);
                    mma_bf16(acc[wm][wn], al[wm], bh[wn]);
                }
        }
        __syncthreads();
    }

    // ---- Epilogue: add bias, store (optionally scatter to q/k/v layout) ----
#pragma unroll
    for (int wm = 0; wm < 4; wm++) {
#pragma unroll
        for (int wn = 0; wn < 4; wn++) {
            int col = n0 + warp_n * 32 + wn * 8 + ((lane & 3) << 1);
            float b0 = __ldg(bias + col), b1 = __ldg(bias + col + 1);
#pragma unroll
            for (int h8 = 0; h8 < 2; h8++) {
                int row = m0 + warp_m * 64 + wm * 16 + (lane >> 2) + h8 * 8;
                float2 o;
                o.x = acc[wm][wn][h8*2+0] + b0;
                o.y = acc[wm][wn][h8*2+1] + b1;
                if (qkv_mode) {
                    int three = col >> 10;
                    int h     = (col & 1023) >> 6;
                    int dcol  = col & 63;
                    float* dst = (three == 0) ? g_q : (three == 1) ? g_k : g_v;
                    int b = row >> 11, t = row & 2047;
                    *(float2*)(dst + ((size_t)(b*H_ + h)*T_ + t) * HD_ + dcol) = o;
                } else {
                    *(float2*)(outp + (size_t)row * D_ + col) = o;
                }
            }
        }
    }
}

// ---------------------------------------------------------------------------
// Flash attention (unchanged known-good fp32 kernel).
// ---------------------------------------------------------------------------
__global__ __launch_bounds__(256) void attn_kernel()
{
    extern __shared__ float sm[];
    float (*Qs)[65] = (float(*)[65])(sm);
    float (*Ks)[65] = (float(*)[65])(sm + 64*65);
    float (*Vs)[65] = (float(*)[65])(sm + 2*64*65);
    float (*Ps)[65] = (float(*)[65])(sm + 3*64*65);

    const int tid = threadIdx.x;
    const int tx = tid & 15, ty = tid >> 4;
    const int qt = blockIdx.x;
    const int bh = blockIdx.y;
    const int m0 = qt << 6;
    const float scale = 0.125f;

    const float* Qg = g_q + (size_t)bh * T_ * HD_;
    const float* Kg = g_k + (size_t)bh * T_ * HD_;
    const float* Vg = g_v + (size_t)bh * T_ * HD_;

#pragma unroll
    for (int l = 0; l < 4; l++) {
        int v = tid + (l << 8);
        int r = v >> 4, c = (v & 15) << 2;
        float4 q4 = *(const float4*)(Qg + (size_t)(m0 + r) * HD_ + c);
        Qs[r][c+0] = q4.x; Qs[r][c+1] = q4.y; Qs[r][c+2] = q4.z; Qs[r][c+3] = q4.w;
    }

    float m_i[4], l_i[4], o[4][4];
#pragma unroll
    for (int i = 0; i < 4; i++) {
        m_i[i] = -1e30f; l_i[i] = 0.0f;
#pragma unroll
        for (int j = 0; j < 4; j++) o[i][j] = 0.0f;
    }

    for (int kt = 0; kt <= qt; kt++) {
        __syncthreads();
#pragma unroll
        for (int l = 0; l < 4; l++) {
            int v = tid + (l << 8);
            int r = v >> 4, c = (v & 15) << 2;
            const size_t gofs = (size_t)((kt << 6) + r) * HD_ + c;
            float4 k4 = *(const float4*)(Kg + gofs);
            Ks[r][c+0] = k4.x; Ks[r][c+1] = k4.y; Ks[r][c+2] = k4.z; Ks[r][c+3] = k4.w;
            float4 v4 = *(const float4*)(Vg + gofs);
            Vs[r][c+0] = v4.x; Vs[r][c+1] = v4.y; Vs[r][c+2] = v4.z; Vs[r][c+3] = v4.w;
        }
        __syncthreads();

        float s[4][4] = {};
#pragma unroll 8
        for (int d = 0; d < 64; d++) {
            float a0 = Qs[ty*4+0][d], a1 = Qs[ty*4+1][d];
            float a2 = Qs[ty*4+2][d], a3 = Qs[ty*4+3][d];
            float b0 = Ks[tx*4+0][d], b1 = Ks[tx*4+1][d];
            float b2 = Ks[tx*4+2][d], b3 = Ks[tx*4+3][d];
            s[0][0] += a0*b0; s[0][1] += a0*b1; s[0][2] += a0*b2; s[0][3] += a0*b3;
            s[1][0] += a1*b0; s[1][1] += a1*b1; s[1][2] += a1*b2; s[1][3] += a1*b3;
            s[2][0] += a2*b0; s[2][1] += a2*b1; s[2][2] += a2*b2; s[2][3] += a2*b3;
            s[3][0] += a3*b0; s[3][1] += a3*b1; s[3][2] += a3*b2; s[3][3] += a3*b3;
        }
#pragma unroll
        for (int i = 0; i < 4; i++)
#pragma unroll
            for (int j = 0; j < 4; j++) s[i][j] *= scale;

        if (kt == qt) {
#pragma unroll
            for (int i = 0; i < 4; i++)
#pragma unroll
                for (int j = 0; j < 4; j++)
                    if ((tx<<2) + j > (ty<<2) + i) s[i][j] = -1e30f;
        }

        float alpha[4];
#pragma unroll
        for (int i = 0; i < 4; i++) {
            float v = fmaxf(fmaxf(s[i][0], s[i][1]), fmaxf(s[i][2], s[i][3]));
#pragma unroll
            for (int off = 1; off < 16; off <<= 1)
                v = fmaxf(v, __shfl_xor_sync(0xffffffffu, v, off));
            float mn = fmaxf(m_i[i], v);
            alpha[i] = __expf(m_i[i] - mn);
            m_i[i] = mn;
        }

        float rs[4];
#pragma unroll
        for (int i = 0; i < 4; i++) {
            rs[i] = 0.0f;
#pragma unroll
            for (int j = 0; j < 4; j++) {
                s[i][j] = __expf(s[i][j] - m_i[i]);
                rs[i] += s[i][j];
            }
#pragma unroll
            for (int off = 1; off < 16; off <<= 1)
                rs[i] += __shfl_xor_sync(0xffffffffu, rs[i], off);
            l_i[i] = l_i[i] * alpha[i] + rs[i];
        }

#pragma unroll
        for (int i = 0; i < 4; i++)
#pragma unroll
            for (int j = 0; j < 4; j++)
                Ps[ty*4+i][tx*4+j] = s[i][j];
        __syncthreads();

#pragma unroll
        for (int i = 0; i < 4; i++)
#pragma unroll
            for (int j = 0; j < 4; j++) o[i][j] *= alpha[i];

#pragma unroll 8
        for (int c = 0; c < 64; c++) {
            float p0 = Ps[ty*4+0][c], p1 = Ps[ty*4+1][c];
            float p2 = Ps[ty*4+2][c], p3 = Ps[ty*4+3][c];
            float v0 = Vs[c][tx*4+0], v1 = Vs[c][tx*4+1];
            float v2 = Vs[c][tx*4+2], v3 = Vs[c][tx*4+3];
            o[0][0] += p0*v0; o[0][1] += p0*v1; o[0][2] += p0*v2; o[0][3] += p0*v3;
            o[1][0] += p1*v0; o[1][1] += p1*v1; o[1][2] += p1*v2; o[1][3] += p1*v3;
            o[2][0] += p2*v0; o[2][1] += p2*v1; o[2][2] += p2*v2; o[2][3] += p2*v3;
            o[3][0] += p3*v0; o[3][1] += p3*v1; o[3][2] += p3*v2; o[3][3] += p3*v3;
        }
    }

    const int b = bh / H_;
    const int h = bh % H_;
#pragma unroll
    for (int i = 0; i < 4; i++) {
        int t = m0 + ty*4 + i;
        float inv = 1.0f / l_i[i];
        float4 r;
        r.x = o[i][0] * inv; r.y = o[i][1] * inv;
        r.z = o[i][2] * inv; r.w = o[i][3] * inv;
        *(float4*)(g_att + (size_t)(b*T_ + t) * D_ + h*HD_ + (tx << 2)) = r;
    }
}

// ---------------------------------------------------------------------------
extern "C" void kernel_launch(void* const* d_in, const int* in_sizes, int n_in,
                              void* d_out, int out_size)
{
    const float* x      = (const float*)d_in[0];
    const float* w_qkv  = (const float*)d_in[1];
    const float* b_qkv  = (const float*)d_in[2];
    const float* w_proj = (const float*)d_in[3];
    const float* b_proj = (const float*)d_in[4];
    float* out = (float*)d_out;

    __nv_bfloat16 *xhi, *xlo, *wqh, *wql, *wph, *wpl, *ahi, *alo;
    cudaGetSymbolAddress((void**)&xhi, g_xhi);
    cudaGetSymbolAddress((void**)&xlo, g_xlo);
    cudaGetSymbolAddress((void**)&wqh, g_wqkv_hi);
    cudaGetSymbolAddress((void**)&wql, g_wqkv_lo);
    cudaGetSymbolAddress((void**)&wph, g_wp_hi);
    cudaGetSymbolAddress((void**)&wpl, g_wp_lo);
    cudaGetSymbolAddress((void**)&ahi, g_atthi);
    cudaGetSymbolAddress((void**)&alo, g_attlo);
    float* attp;
    cudaGetSymbolAddress((void**)&attp, g_att);

    cudaFuncSetAttribute(hmma_gemm_kernel,
                         cudaFuncAttributeMaxDynamicSharedMemorySize, GEMM_SMEM);
    const int attn_smem = 4 * 64 * 65 * (int)sizeof(float);
    cudaFuncSetAttribute(attn_kernel,
                         cudaFuncAttributeMaxDynamicSharedMemorySize, attn_smem);

    // 1) split X, transpose+split weights
    split_kernel<<<(M_*D_/4 + 255)/256, 256>>>(x, xhi, xlo, M_*D_/4);
    transpose_split_kernel<<<dim3(NQKV/32, D_/32), dim3(32, 8)>>>(w_qkv, wqh, wql, D_, NQKV);
    transpose_split_kernel<<<dim3(D_/32,  D_/32), dim3(32, 8)>>>(w_proj, wph, wpl, D_, D_);

    // 2) QKV HMMA GEMM -> g_q/g_k/g_v
    hmma_gemm_kernel<<<dim3(NQKV/128, M_/128), 256, GEMM_SMEM>>>(
        xhi, xlo, wqh, wql, b_qkv, nullptr, 1);

    // 3) causal flash attention (fp32)
    attn_kernel<<<dim3(T_/64, B_*H_), 256, attn_smem>>>();

    // 4) split attention output, proj HMMA GEMM -> out
    split_kernel<<<(M_*D_/4 + 255)/256, 256>>>(attp, ahi, alo, M_*D_/4);
    hmma_gemm_kernel<<<dim3(D_/128, M_/128), 256, GEMM_SMEM>>>(
        ahi, alo, wph, wpl, b_proj, out, 0);
}

// round 9
// speedup vs baseline: 2.6810x; 1.5756x over previous
#include <cuda_runtime.h>
#include <cuda_bf16.h>
#include <cstdint>

#define B_  4
#define T_  2048
#define D_  1024
#define H_  16
#define HD_ 64
#define M_  (B_*T_)
#define NQKV (3*D_)
#define GK   1024

// ---------------------------------------------------------------------------
// Scratch (allocation-free __device__ globals)
// ---------------------------------------------------------------------------
__device__ float g_att[(size_t)M_*D_];

// split-bf16 operands for the dense GEMMs
__device__ __nv_bfloat16 g_xhi[(size_t)M_*D_];
__device__ __nv_bfloat16 g_xlo[(size_t)M_*D_];
__device__ __nv_bfloat16 g_wqkv_hi[(size_t)NQKV*D_];   // transposed [N,K]
__device__ __nv_bfloat16 g_wqkv_lo[(size_t)NQKV*D_];
__device__ __nv_bfloat16 g_wp_hi[(size_t)D_*D_];       // transposed [N,K]
__device__ __nv_bfloat16 g_wp_lo[(size_t)D_*D_];
__device__ __nv_bfloat16 g_atthi[(size_t)M_*D_];
__device__ __nv_bfloat16 g_attlo[(size_t)M_*D_];

// split-bf16 Q/K/V in [B,H,T,Hd] layout (Q pre-scaled by 1/sqrt(Hd))
__device__ __nv_bfloat16 g_qhi[(size_t)B_*H_*T_*HD_];
__device__ __nv_bfloat16 g_qlo[(size_t)B_*H_*T_*HD_];
__device__ __nv_bfloat16 g_khi[(size_t)B_*H_*T_*HD_];
__device__ __nv_bfloat16 g_klo[(size_t)B_*H_*T_*HD_];
__device__ __nv_bfloat16 g_vhi[(size_t)B_*H_*T_*HD_];
__device__ __nv_bfloat16 g_vlo[(size_t)B_*H_*T_*HD_];

// ---------------------------------------------------------------------------
// Helpers (plain sm_80+ PTX; nothing arch-'a'-gated)
// ---------------------------------------------------------------------------
__device__ __forceinline__ uint32_t smem_u32_of(const void* p) {
    uint32_t a;
    asm("{ .reg .u64 t; cvta.to.shared.u64 t, %1; cvt.u32.u64 %0, t; }" : "=r"(a) : "l"(p));
    return a;
}

__device__ __forceinline__ void cp_async16(uint32_t saddr, const void* gptr) {
    asm volatile("cp.async.cg.shared.global [%0], [%1], 16;"
                 :: "r"(saddr), "l"(gptr) : "memory");
}

__device__ __forceinline__ void mma_bf16(float* c, const uint32_t* a, const uint32_t* b) {
    asm volatile(
        "mma.sync.aligned.m16n8k16.row.col.f32.bf16.bf16.f32 "
        "{%0,%1,%2,%3}, {%4,%5,%6,%7}, {%8,%9}, {%0,%1,%2,%3};"
        : "+f"(c[0]), "+f"(c[1]), "+f"(c[2]), "+f"(c[3])
        : "r"(a[0]), "r"(a[1]), "r"(a[2]), "r"(a[3]), "r"(b[0]), "r"(b[1]));
}

__device__ __forceinline__ void packsplit2(float x, float y, uint32_t& hi, uint32_t& lo) {
    __nv_bfloat162 h = __floats2bfloat162_rn(x, y);
    float rx = x - __bfloat162float(h.x);
    float ry = y - __bfloat162float(h.y);
    __nv_bfloat162 l = __floats2bfloat162_rn(rx, ry);
    hi = *(uint32_t*)&h;
    lo = *(uint32_t*)&l;
}

// ---------------------------------------------------------------------------
// Split fp32 -> (hi, lo) bf16, elementwise
// ---------------------------------------------------------------------------
__global__ __launch_bounds__(256) void split_kernel(
    const float* __restrict__ in, __nv_bfloat16* __restrict__ hi,
    __nv_bfloat16* __restrict__ lo, int n4)
{
    int i = blockIdx.x * blockDim.x + threadIdx.x;
    if (i >= n4) return;
    float4 v = ((const float4*)in)[i];
    __nv_bfloat16 h0 = __float2bfloat16(v.x), h1 = __float2bfloat16(v.y);
    __nv_bfloat16 h2 = __float2bfloat16(v.z), h3 = __float2bfloat16(v.w);
    __nv_bfloat16 l0 = __float2bfloat16(v.x - __bfloat162float(h0));
    __nv_bfloat16 l1 = __float2bfloat16(v.y - __bfloat162float(h1));
    __nv_bfloat16 l2 = __float2bfloat16(v.z - __bfloat162float(h2));
    __nv_bfloat16 l3 = __float2bfloat16(v.w - __bfloat162float(h3));
    ((__nv_bfloat162*)hi)[i*2+0] = __nv_bfloat162(h0, h1);
    ((__nv_bfloat162*)hi)[i*2+1] = __nv_bfloat162(h2, h3);
    ((__nv_bfloat162*)lo)[i*2+0] = __nv_bfloat162(l0, l1);
    ((__nv_bfloat162*)lo)[i*2+1] = __nv_bfloat162(l2, l3);
}

// ---------------------------------------------------------------------------
// Transpose + split: W[K,N] fp32 -> Wt_hi/lo[N,K] bf16
// ---------------------------------------------------------------------------
__global__ __launch_bounds__(256) void transpose_split_kernel(
    const float* __restrict__ W, __nv_bfloat16* __restrict__ hi,
    __nv_bfloat16* __restrict__ lo, int K, int N)
{
    __shared__ float tile[32][33];
    const int tx = threadIdx.x, ty = threadIdx.y;
    const int n0 = blockIdx.x * 32, k0 = blockIdx.y * 32;
#pragma unroll
    for (int i = 0; i < 32; i += 8)
        tile[ty + i][tx] = W[(size_t)(k0 + ty + i) * N + n0 + tx];
    __syncthreads();
#pragma unroll
    for (int i = 0; i < 32; i += 8) {
        float v = tile[tx][ty + i];
        __nv_bfloat16 h = __float2bfloat16(v);
        __nv_bfloat16 l = __float2bfloat16(v - __bfloat162float(h));
        size_t o = (size_t)(n0 + ty + i) * K + (k0 + tx);
        hi[o] = h; lo[o] = l;
    }
}

// ---------------------------------------------------------------------------
// HMMA split-bf16 GEMM (verified Round 6). qkv_mode epilogue writes
// bf16 hi/lo Q(scaled)/K/V in [B,H,T,Hd]; else fp32 outp.
// ---------------------------------------------------------------------------
#define BKC      32
#define NCHUNK   (GK/BKC)
#define ROW_W    20
#define OPB      10240
#define STAGE_B  (4*OPB)
#define GEMM_SMEM (2*STAGE_B)

__global__ __launch_bounds__(256) void hmma_gemm_kernel(
    const __nv_bfloat16* __restrict__ Ahi, const __nv_bfloat16* __restrict__ Alo,
    const __nv_bfloat16* __restrict__ Bhi, const __nv_bfloat16* __restrict__ Blo,
    const float* __restrict__ bias, float* __restrict__ outp, int qkv_mode)
{
    extern __shared__ char smem[];
    const int tid  = threadIdx.x;
    const int lane = tid & 31;
    const int wid  = tid >> 5;
    const int warp_m = wid & 1;
    const int warp_n = wid >> 1;
    const int n0 = blockIdx.x << 7;
    const int m0 = blockIdx.y << 7;

    const __nv_bfloat16* gops[4] = {
        Ahi + (size_t)m0 * GK, Alo + (size_t)m0 * GK,
        Bhi + (size_t)n0 * GK, Blo + (size_t)n0 * GK };

    auto stage_load = [&](int c, int s) {
#pragma unroll
        for (int op = 0; op < 4; op++) {
            char* sd = smem + s * STAGE_B + op * OPB;
            const __nv_bfloat16* g = gops[op];
#pragma unroll
            for (int rep = 0; rep < 2; rep++) {
                int idx = tid + (rep << 8);
                int row = idx >> 2, q = idx & 3;
                uint32_t da = smem_u32_of(sd + row * 80 + q * 16);
                cp_async16(da, (const char*)(g + (size_t)row * GK + c * BKC) + q * 16);
            }
        }
    };

    float acc[4][4][4];
#pragma unroll
    for (int i = 0; i < 4; i++)
#pragma unroll
        for (int j = 0; j < 4; j++)
#pragma unroll
            for (int r = 0; r < 4; r++) acc[i][j][r] = 0.0f;

    stage_load(0, 0);
    asm volatile("cp.async.commit_group;" ::: "memory");

    for (int c = 0; c < NCHUNK; c++) {
        if (c + 1 < NCHUNK) {
            stage_load(c + 1, (c + 1) & 1);
            asm volatile("cp.async.commit_group;" ::: "memory");
            asm volatile("cp.async.wait_group 1;" ::: "memory");
        } else {
            asm volatile("cp.async.wait_group 0;" ::: "memory");
        }
        __syncthreads();

        const uint32_t* sAh = (const uint32_t*)(smem + (c & 1) * STAGE_B);
        const uint32_t* sAl = sAh + OPB / 4;
        const uint32_t* sBh = sAl + OPB / 4;
        const uint32_t* sBl = sBh + OPB / 4;

#pragma unroll
        for (int ks = 0; ks < 2; ks++) {
            const int aw = ks * 8 + (lane & 3);
            const int ar = warp_m * 64 + (lane >> 2);
            uint32_t ah[4][4], al[4][4], bh[4][2], bl[4][2];
#pragma unroll
            for (int wm = 0; wm < 4; wm++) {
                int r0 = (ar + wm * 16) * ROW_W;
                int r8 = (ar + wm * 16 + 8) * ROW_W;
                ah[wm][0] = sAh[r0 + aw];   ah[wm][1] = sAh[r8 + aw];
                ah[wm][2] = sAh[r0 + aw+4]; ah[wm][3] = sAh[r8 + aw+4];
                al[wm][0] = sAl[r0 + aw];   al[wm][1] = sAl[r8 + aw];
                al[wm][2] = sAl[r0 + aw+4]; al[wm][3] = sAl[r8 + aw+4];
            }
#pragma unroll
            for (int wn = 0; wn < 4; wn++) {
                int br = (warp_n * 32 + wn * 8 + (lane >> 2)) * ROW_W;
                bh[wn][0] = sBh[br + aw]; bh[wn][1] = sBh[br + aw + 4];
                bl[wn][0] = sBl[br + aw]; bl[wn][1] = sBl[br + aw + 4];
            }
#pragma unroll
            for (int wm = 0; wm < 4; wm++)
#pragma unroll
                for (int wn = 0; wn < 4; wn++) {
                    mma_bf16(acc[wm][wn], ah[wm], bh[wn]);
                    mma_bf16(acc[wm][wn], ah[wm], bl[wn]);
                    mma_bf16(acc[wm][wn], al[wm], bh[wn]);
                }
        }
        __syncthreads();
    }

    // ---- Epilogue ----
#pragma unroll
    for (int wm = 0; wm < 4; wm++) {
#pragma unroll
        for (int wn = 0; wn < 4; wn++) {
            int col = n0 + warp_n * 32 + wn * 8 + ((lane & 3) << 1);
            float b0 = __ldg(bias + col), b1 = __ldg(bias + col + 1);
#pragma unroll
            for (int h8 = 0; h8 < 2; h8++) {
                int row = m0 + warp_m * 64 + wm * 16 + (lane >> 2) + h8 * 8;
                float v0 = acc[wm][wn][h8*2+0] + b0;
                float v1 = acc[wm][wn][h8*2+1] + b1;
                if (qkv_mode) {
                    int three = col >> 10;
                    int h     = (col & 1023) >> 6;
                    int dcol  = col & 63;
                    if (three == 0) { v0 *= 0.125f; v1 *= 0.125f; }   // fold 1/sqrt(64)
                    __nv_bfloat16* dh = (three == 0) ? g_qhi : (three == 1) ? g_khi : g_vhi;
                    __nv_bfloat16* dl = (three == 0) ? g_qlo : (three == 1) ? g_klo : g_vlo;
                    uint32_t phv, plv;
                    packsplit2(v0, v1, phv, plv);
                    int b = row >> 11, t = row & 2047;
                    size_t o = ((size_t)(b*H_ + h)*T_ + t) * HD_ + dcol;
                    *(uint32_t*)(dh + o) = phv;
                    *(uint32_t*)(dl + o) = plv;
                } else {
                    float2 o2; o2.x = v0; o2.y = v1;
                    *(float2*)(outp + (size_t)row * D_ + col) = o2;
                }
            }
        }
    }
}

// ---------------------------------------------------------------------------
// HMMA flash attention. Block = 128 q rows, 8 warps (16 rows each), key tiles
// of 64. Split-bf16 3-term for both S=QK^T and O=PV. Online softmax in
// accumulator-fragment layout; P converted register-to-register.
// ---------------------------------------------------------------------------
#define KSTR 72          // padded smem row: 72 bf16 = 36 words (conflict-free)

__global__ __launch_bounds__(256) void attn_mma_kernel()
{
    __shared__ __nv_bfloat16 sK[2][64*KSTR];    // [hi/lo][token][dim]
    __shared__ __nv_bfloat16 sVt[2][64*KSTR];   // [hi/lo][dim][token]

    const int tid = threadIdx.x, lane = tid & 31, wid = tid >> 5;
    const int qb = blockIdx.x, bh = blockIdx.y;
    const int m0 = qb << 7;
    const int r4 = lane >> 2, c4 = lane & 3;
    const int rowblk = wid * 16 + r4;            // row within 128-block (and +8)

    const size_t bho = (size_t)bh * T_ * HD_;
    const __nv_bfloat16* Kh = g_khi + bho;
    const __nv_bfloat16* Kl = g_klo + bho;
    const __nv_bfloat16* Vh = g_vhi + bho;
    const __nv_bfloat16* Vl = g_vlo + bho;

    // ---- Q fragments (pre-scaled), held in registers for the whole sweep ----
    uint32_t qa[2][4][4];
    {
        const __nv_bfloat16* srcs[2] = { g_qhi + bho, g_qlo + bho };
#pragma unroll
        for (int hl = 0; hl < 2; hl++) {
            const __nv_bfloat16* S = srcs[hl];
            const size_t r0 = (size_t)(m0 + rowblk) * HD_;
            const size_t r8 = r0 + 8 * HD_;
#pragma unroll
            for (int ks = 0; ks < 4; ks++) {
                int col0 = ks * 16 + 2 * c4;
                qa[hl][ks][0] = *(const uint32_t*)(S + r0 + col0);
                qa[hl][ks][1] = *(const uint32_t*)(S + r8 + col0);
                qa[hl][ks][2] = *(const uint32_t*)(S + r0 + col0 + 8);
                qa[hl][ks][3] = *(const uint32_t*)(S + r8 + col0 + 8);
            }
        }
    }

    float m_i[2] = { -1e30f, -1e30f };
    float l_i[2] = { 0.0f, 0.0f };
    float o[8][4];
#pragma unroll
    for (int j = 0; j < 8; j++)
#pragma unroll
        for (int r = 0; r < 4; r++) o[j][r] = 0.0f;

    const int ktmax = 2 * qb + 1;
    for (int kt = 0; kt <= ktmax; kt++) {
        if (kt) __syncthreads();     // previous tile's consumers done

        // K tiles via cp.async ([token][dim], 128B rows)
#pragma unroll
        for (int hl = 0; hl < 2; hl++) {
            const __nv_bfloat16* src = hl ? Kl : Kh;
#pragma unroll
            for (int rep = 0; rep < 2; rep++) {
                int idx = tid + (rep << 8);          // 0..511
                int row = idx >> 3, ch = idx & 7;
                uint32_t da = smem_u32_of(&sK[hl][row * KSTR]) + ch * 16;
                cp_async16(da, (const char*)(src + (size_t)(kt*64 + row) * HD_) + ch * 16);
            }
        }
        asm volatile("cp.async.commit_group;" ::: "memory");

        // V tiles: load [token][dim], store transposed [dim][token]
#pragma unroll
        for (int hl = 0; hl < 2; hl++) {
            const __nv_bfloat16* src = hl ? Vl : Vh;
#pragma unroll
            for (int rep = 0; rep < 4; rep++) {
                int idx = tid + (rep << 8);          // 0..1023
                int t = idx >> 4, dg = (idx & 15) << 2;
                uint2 v = *(const uint2*)(src + (size_t)(kt*64 + t) * HD_ + dg);
                __nv_bfloat162 p0 = *(__nv_bfloat162*)&v.x;
                __nv_bfloat162 p1 = *(__nv_bfloat162*)&v.y;
                sVt[hl][(dg+0)*KSTR + t] = p0.x;
                sVt[hl][(dg+1)*KSTR + t] = p0.y;
                sVt[hl][(dg+2)*KSTR + t] = p1.x;
                sVt[hl][(dg+3)*KSTR + t] = p1.y;
            }
        }
        asm volatile("cp.async.wait_group 0;" ::: "memory");
        __syncthreads();

        const bool active = !(kt == ktmax && wid < 4);   // lower half skips last tile
        if (active) {
            // ---- S = Q K^T (3-term split), 16x64 per warp ----
            float s[8][4];
#pragma unroll
            for (int j = 0; j < 8; j++)
#pragma unroll
                for (int r = 0; r < 4; r++) s[j][r] = 0.0f;

            const uint32_t* wKh = (const uint32_t*)sK[0];
            const uint32_t* wKl = (const uint32_t*)sK[1];
#pragma unroll
            for (int ks = 0; ks < 4; ks++) {
                const int w0 = ks * 8 + c4;
#pragma unroll
                for (int j = 0; j < 8; j++) {
                    int br = (j * 8 + r4) * 36;
                    uint32_t kb[2] = { wKh[br + w0], wKh[br + w0 + 4] };
                    uint32_t kl2[2] = { wKl[br + w0], wKl[br + w0 + 4] };
                    mma_bf16(s[j], qa[0][ks], kb);
                    mma_bf16(s[j], qa[0][ks], kl2);
                    mma_bf16(s[j], qa[1][ks], kb);
                }
            }

            // ---- causal mask (only near/on the diagonal) ----
            if (kt >= 2 * qb) {
                int kbase = (kt - 2 * qb) << 6;
#pragma unroll
                for (int j = 0; j < 8; j++) {
                    int col = kbase + j * 8 + 2 * c4;
                    if (col     > rowblk)     s[j][0] = -1e30f;
                    if (col + 1 > rowblk)     s[j][1] = -1e30f;
                    if (col     > rowblk + 8) s[j][2] = -1e30f;
                    if (col + 1 > rowblk + 8) s[j][3] = -1e30f;
                }
            }

            // ---- online softmax (rows rowblk, rowblk+8; quad reduction) ----
            float mx0 = -1e30f, mx1 = -1e30f;
#pragma unroll
            for (int j = 0; j < 8; j++) {
                mx0 = fmaxf(mx0, fmaxf(s[j][0], s[j][1]));
                mx1 = fmaxf(mx1, fmaxf(s[j][2], s[j][3]));
            }
            mx0 = fmaxf(mx0, __shfl_xor_sync(0xffffffffu, mx0, 1));
            mx0 = fmaxf(mx0, __shfl_xor_sync(0xffffffffu, mx0, 2));
            mx1 = fmaxf(mx1, __shfl_xor_sync(0xffffffffu, mx1, 1));
            mx1 = fmaxf(mx1, __shfl_xor_sync(0xffffffffu, mx1, 2));

            float mn0 = fmaxf(m_i[0], mx0), mn1 = fmaxf(m_i[1], mx1);
            float al0 = __expf(m_i[0] - mn0), al1 = __expf(m_i[1] - mn1);
            m_i[0] = mn0; m_i[1] = mn1;

            float rs0 = 0.0f, rs1 = 0.0f;
#pragma unroll
            for (int j = 0; j < 8; j++) {
                s[j][0] = __expf(s[j][0] - mn0);
                s[j][1] = __expf(s[j][1] - mn0);
                s[j][2] = __expf(s[j][2] - mn1);
                s[j][3] = __expf(s[j][3] - mn1);
                rs0 += s[j][0] + s[j][1];
                rs1 += s[j][2] + s[j][3];
            }
            rs0 += __shfl_xor_sync(0xffffffffu, rs0, 1);
            rs0 += __shfl_xor_sync(0xffffffffu, rs0, 2);
            rs1 += __shfl_xor_sync(0xffffffffu, rs1, 1);
            rs1 += __shfl_xor_sync(0xffffffffu, rs1, 2);
            l_i[0] = l_i[0] * al0 + rs0;
            l_i[1] = l_i[1] * al1 + rs1;

#pragma unroll
            for (int j = 0; j < 8; j++) {
                o[j][0] *= al0; o[j][1] *= al0;
                o[j][2] *= al1; o[j][3] *= al1;
            }

            // ---- O += P V (3-term split), P converted in registers ----
            const uint32_t* wVh = (const uint32_t*)sVt[0];
            const uint32_t* wVl = (const uint32_t*)sVt[1];
#pragma unroll
            for (int ks = 0; ks < 4; ks++) {
                uint32_t pah[4], pal[4];
                packsplit2(s[2*ks  ][0], s[2*ks  ][1], pah[0], pal[0]);
                packsplit2(s[2*ks  ][2], s[2*ks  ][3], pah[1], pal[1]);
                packsplit2(s[2*ks+1][0], s[2*ks+1][1], pah[2], pal[2]);
                packsplit2(s[2*ks+1][2], s[2*ks+1][3], pah[3], pal[3]);
                const int w0 = ks * 8 + c4;
#pragma unroll
                for (int j = 0; j < 8; j++) {
                    int br = (j * 8 + r4) * 36;
                    uint32_t vb[2] = { wVh[br + w0], wVh[br + w0 + 4] };
                    uint32_t vl2[2] = { wVl[br + w0], wVl[br + w0 + 4] };
                    mma_bf16(o[j], pah, vb);
                    mma_bf16(o[j], pah, vl2);
                    mma_bf16(o[j], pal, vb);
                }
            }
        }
    }

    // ---- normalize, write to g_att [B,T,D] ----
    float inv0 = 1.0f / l_i[0], inv1 = 1.0f / l_i[1];
    const int b = bh >> 4, h = bh & 15;
    const int t0 = m0 + rowblk, t1 = t0 + 8;
#pragma unroll
    for (int j = 0; j < 8; j++) {
        int dim = h * 64 + j * 8 + 2 * c4;
        float2 w0; w0.x = o[j][0] * inv0; w0.y = o[j][1] * inv0;
        float2 w1; w1.x = o[j][2] * inv1; w1.y = o[j][3] * inv1;
        *(float2*)(g_att + (size_t)(b*T_ + t0) * D_ + dim) = w0;
        *(float2*)(g_att + (size_t)(b*T_ + t1) * D_ + dim) = w1;
    }
}

// ---------------------------------------------------------------------------
extern "C" void kernel_launch(void* const* d_in, const int* in_sizes, int n_in,
                              void* d_out, int out_size)
{
    const float* x      = (const float*)d_in[0];
    const float* w_qkv  = (const float*)d_in[1];
    const float* b_qkv  = (const float*)d_in[2];
    const float* w_proj = (const float*)d_in[3];
    const float* b_proj = (const float*)d_in[4];
    float* out = (float*)d_out;

    __nv_bfloat16 *xhi, *xlo, *wqh, *wql, *wph, *wpl, *ahi, *alo;
    cudaGetSymbolAddress((void**)&xhi, g_xhi);
    cudaGetSymbolAddress((void**)&xlo, g_xlo);
    cudaGetSymbolAddress((void**)&wqh, g_wqkv_hi);
    cudaGetSymbolAddress((void**)&wql, g_wqkv_lo);
    cudaGetSymbolAddress((void**)&wph, g_wp_hi);
    cudaGetSymbolAddress((void**)&wpl, g_wp_lo);
    cudaGetSymbolAddress((void**)&ahi, g_atthi);
    cudaGetSymbolAddress((void**)&alo, g_attlo);
    float* attp;
    cudaGetSymbolAddress((void**)&attp, g_att);

    cudaFuncSetAttribute(hmma_gemm_kernel,
                         cudaFuncAttributeMaxDynamicSharedMemorySize, GEMM_SMEM);

    // 1) split X, transpose+split weights
    split_kernel<<<(M_*D_/4 + 255)/256, 256>>>(x, xhi, xlo, M_*D_/4);
    transpose_split_kernel<<<dim3(NQKV/32, D_/32), dim3(32, 8)>>>(w_qkv, wqh, wql, D_, NQKV);
    transpose_split_kernel<<<dim3(D_/32,  D_/32), dim3(32, 8)>>>(w_proj, wph, wpl, D_, D_);

    // 2) QKV HMMA GEMM -> split-bf16 q/k/v (q pre-scaled)
    hmma_gemm_kernel<<<dim3(NQKV/128, M_/128), 256, GEMM_SMEM>>>(
        xhi, xlo, wqh, wql, b_qkv, nullptr, 1);

    // 3) HMMA flash attention -> g_att fp32
    attn_mma_kernel<<<dim3(T_/128, B_*H_), 256>>>();

    // 4) split attention output, proj HMMA GEMM -> out
    split_kernel<<<(M_*D_/4 + 255)/256, 256>>>(attp, ahi, alo, M_*D_/4);
    hmma_gemm_kernel<<<dim3(D_/128, M_/128), 256, GEMM_SMEM>>>(
        ahi, alo, wph, wpl, b_proj, out, 0);
}